// round 1
// baseline (speedup 1.0000x reference)
#include <cuda_runtime.h>
#include <math.h>

// Problem constants (fixed instance)
#define MDIM 131072   // B*N
#define KDIM 512      // D
#define NDIM 512      // H
#define NNODES 2048
#define HALFN 1024

// Scratch (allowed: __device__ globals, no runtime alloc)
__device__ float  g_h[(size_t)MDIM * NDIM];   // 256 MB hidden activations
__device__ double g_sum[NDIM];
__device__ double g_sumsq[NDIM];
__device__ float  g_a[NDIM];
__device__ float  g_c[NDIM];

// ---------------------------------------------------------------------------
// K0: zero the stats accumulators (graph replays must be deterministic)
// ---------------------------------------------------------------------------
__global__ void zero_stats_kernel() {
    int j = threadIdx.x;
    g_sum[j] = 0.0;
    g_sumsq[j] = 0.0;
}

// ---------------------------------------------------------------------------
// K1: fp32 GEMM  h = x @ W1 + b1   (M=131072, K=512, N=512)
// 128x128 tile per block, 256 threads, 8x8 per-thread microtile split as
// (4 rows @ ty*4, 4 rows @ 64+ty*4) x (4 cols @ tx*4, 4 cols @ 64+tx*4)
// so shared loads are conflict-free float4.
// ---------------------------------------------------------------------------
__global__ void __launch_bounds__(256) gemm_kernel(const float* __restrict__ A,
                                                   const float* __restrict__ B,
                                                   const float* __restrict__ bias,
                                                   float* __restrict__ C) {
    __shared__ float sA[16][132];   // [k][m], padded
    __shared__ float sB[16][132];   // [k][n], padded

    const int tid = threadIdx.x;
    const int m0 = blockIdx.y * 128;
    const int n0 = blockIdx.x * 128;
    const int ty = tid >> 4;        // 0..15
    const int tx = tid & 15;        // 0..15

    // global-load indices
    const int arow = tid >> 2;          // 0..63
    const int akf  = (tid & 3) * 4;     // k offset within 16-chunk
    const int bk   = tid >> 5;          // 0..7
    const int bnf  = (tid & 31) * 4;    // col offset 0..124

    float acc[8][8];
#pragma unroll
    for (int i = 0; i < 8; i++)
#pragma unroll
        for (int j = 0; j < 8; j++) acc[i][j] = 0.f;

    for (int k0 = 0; k0 < KDIM; k0 += 16) {
        // A tile: 128 rows x 16 k (transposed into sA[k][m])
#pragma unroll
        for (int i = 0; i < 2; i++) {
            int r = arow + i * 64;
            float4 v = *(const float4*)&A[(size_t)(m0 + r) * KDIM + k0 + akf];
            sA[akf + 0][r] = v.x;
            sA[akf + 1][r] = v.y;
            sA[akf + 2][r] = v.z;
            sA[akf + 3][r] = v.w;
        }
        // B tile: 16 k x 128 cols
#pragma unroll
        for (int i = 0; i < 2; i++) {
            int kk = bk + i * 8;
            float4 v = *(const float4*)&B[(size_t)(k0 + kk) * NDIM + n0 + bnf];
            *(float4*)&sB[kk][bnf] = v;
        }
        __syncthreads();

#pragma unroll
        for (int kk = 0; kk < 16; kk++) {
            float4 a0 = *(float4*)&sA[kk][ty * 4];
            float4 a1 = *(float4*)&sA[kk][64 + ty * 4];
            float4 b0 = *(float4*)&sB[kk][tx * 4];
            float4 b1 = *(float4*)&sB[kk][64 + tx * 4];
            float av[8] = {a0.x, a0.y, a0.z, a0.w, a1.x, a1.y, a1.z, a1.w};
            float bv[8] = {b0.x, b0.y, b0.z, b0.w, b1.x, b1.y, b1.z, b1.w};
#pragma unroll
            for (int i = 0; i < 8; i++)
#pragma unroll
                for (int j = 0; j < 8; j++) acc[i][j] = fmaf(av[i], bv[j], acc[i][j]);
        }
        __syncthreads();
    }

    // epilogue: add bias, store
#pragma unroll
    for (int i = 0; i < 8; i++) {
        int m = m0 + ((i < 4) ? (ty * 4 + i) : (64 + ty * 4 + i - 4));
#pragma unroll
        for (int jh = 0; jh < 2; jh++) {
            int n = n0 + ((jh == 0) ? (tx * 4) : (64 + tx * 4));
            float4 bsv = *(const float4*)&bias[n];
            float4 o;
            o.x = acc[i][jh * 4 + 0] + bsv.x;
            o.y = acc[i][jh * 4 + 1] + bsv.y;
            o.z = acc[i][jh * 4 + 2] + bsv.z;
            o.w = acc[i][jh * 4 + 3] + bsv.w;
            *(float4*)&C[(size_t)m * NDIM + n] = o;
        }
    }
}

// ---------------------------------------------------------------------------
// K2: per-column sum / sumsq over all rows (coalesced; fp32 partials over
// 1024 rows, fp64 atomics for the global combine)
// ---------------------------------------------------------------------------
__global__ void __launch_bounds__(512) stats_kernel(const float* __restrict__ Hbuf) {
    const int col = threadIdx.x;
    const size_t base = (size_t)blockIdx.x * 1024 * NDIM;
    float s = 0.f, s2 = 0.f;
    for (int r = 0; r < 1024; r++) {
        float v = Hbuf[base + (size_t)r * NDIM + col];
        s += v;
        s2 = fmaf(v, v, s2);
    }
    atomicAdd(&g_sum[col], (double)s);
    atomicAdd(&g_sumsq[col], (double)s2);
}

// ---------------------------------------------------------------------------
// K3: finalize BN affine:  a = gamma * rsqrt(var+eps),  c = beta - mu*a
// ---------------------------------------------------------------------------
__global__ void finalize_kernel(const float* __restrict__ gamma,
                                const float* __restrict__ beta) {
    int j = threadIdx.x;
    double mu = g_sum[j] / (double)MDIM;
    double var = g_sumsq[j] / (double)MDIM - mu * mu;
    double a = (double)gamma[j] / sqrt(var + 1e-5);
    g_a[j] = (float)a;
    g_c[j] = (float)((double)beta[j] - mu * a);
}

// ---------------------------------------------------------------------------
// K4: per-row heads. One warp per row: affine+ReLU the 512-vector, dot with
// Wa (3 cls) or Wb (5 cls), warp-reduce, argmax (first-max tiebreak).
// ---------------------------------------------------------------------------
__global__ void __launch_bounds__(256) heads_kernel(const float* __restrict__ Hbuf,
                                                    const float* __restrict__ Wa,
                                                    const float* __restrict__ ba,
                                                    const float* __restrict__ Wb,
                                                    const float* __restrict__ bb,
                                                    float* __restrict__ out) {
    const int row = (int)((blockIdx.x * blockDim.x + threadIdx.x) >> 5);
    const int lane = threadIdx.x & 31;
    if (row >= MDIM) return;
    const int n = row & (NNODES - 1);
    const bool isA = (n < HALFN);

    const float4* h4 = (const float4*)(Hbuf + (size_t)row * NDIM);
    const float4* ga4 = (const float4*)g_a;
    const float4* gc4 = (const float4*)g_c;

    float acc[5] = {0.f, 0.f, 0.f, 0.f, 0.f};

#pragma unroll
    for (int i = 0; i < 4; i++) {
        int j4 = i * 32 + lane;       // float4 index; columns 4*j4..4*j4+3
        float4 v = h4[j4];
        float4 a4 = ga4[j4];
        float4 c4 = gc4[j4];
        float t[4];
        t[0] = fmaxf(fmaf(v.x, a4.x, c4.x), 0.f);
        t[1] = fmaxf(fmaf(v.y, a4.y, c4.y), 0.f);
        t[2] = fmaxf(fmaf(v.z, a4.z, c4.z), 0.f);
        t[3] = fmaxf(fmaf(v.w, a4.w, c4.w), 0.f);
        if (isA) {
#pragma unroll
            for (int e = 0; e < 4; e++) {
                int j = j4 * 4 + e;
#pragma unroll
                for (int c = 0; c < 3; c++) acc[c] = fmaf(t[e], Wa[j * 3 + c], acc[c]);
            }
        } else {
#pragma unroll
            for (int e = 0; e < 4; e++) {
                int j = j4 * 4 + e;
#pragma unroll
                for (int c = 0; c < 5; c++) acc[c] = fmaf(t[e], Wb[j * 5 + c], acc[c]);
            }
        }
    }

    // warp reduction
#pragma unroll
    for (int off = 16; off > 0; off >>= 1) {
#pragma unroll
        for (int c = 0; c < 5; c++) acc[c] += __shfl_down_sync(0xFFFFFFFFu, acc[c], off);
    }

    if (lane == 0) {
        int C = isA ? 3 : 5;
        const float* bvec = isA ? ba : bb;
        int best = 0;
        float bestv = acc[0] + bvec[0];
#pragma unroll
        for (int c = 1; c < 5; c++) {
            if (c < C) {
                float lv = acc[c] + bvec[c];
                if (lv > bestv) { bestv = lv; best = c; }
            }
        }
        out[row] = (float)best;
    }
}

// ---------------------------------------------------------------------------
// launch
// ---------------------------------------------------------------------------
extern "C" void kernel_launch(void* const* d_in, const int* in_sizes, int n_in,
                              void* d_out, int out_size) {
    const float* x     = (const float*)d_in[0];
    const float* W1    = (const float*)d_in[1];
    const float* b1    = (const float*)d_in[2];
    const float* gamma = (const float*)d_in[3];
    const float* beta  = (const float*)d_in[4];
    const float* Wa    = (const float*)d_in[5];
    const float* ba    = (const float*)d_in[6];
    const float* Wb    = (const float*)d_in[7];
    const float* bb    = (const float*)d_in[8];
    float* out = (float*)d_out;

    float* Hbuf;
    cudaGetSymbolAddress((void**)&Hbuf, g_h);

    zero_stats_kernel<<<1, NDIM>>>();

    dim3 ggrid(NDIM / 128, MDIM / 128);
    gemm_kernel<<<ggrid, 256>>>(x, W1, b1, Hbuf);

    stats_kernel<<<MDIM / 1024, 512>>>(Hbuf);

    finalize_kernel<<<1, NDIM>>>(gamma, beta);

    int warps = MDIM;
    int threads = 256;
    int blocks = (warps * 32 + threads - 1) / threads;
    heads_kernel<<<blocks, threads>>>(Hbuf, Wa, ba, Wb, bb, out);
}

// round 3
// speedup vs baseline: 1.1422x; 1.1422x over previous
#include <cuda_runtime.h>
#include <cuda_bf16.h>
#include <stdint.h>
#include <math.h>

// ---------------- problem constants ----------------
#define MDIM 131072   // B*N rows
#define KDIM 512      // D
#define NDIM 512      // H
#define NNODES 2048
#define HALFN 1024

#define TILE_M 128
#define TILE_N 256
#define KC 32
#define NCHUNK 16

// smem layout (bytes from 128-aligned dynamic base):
//   A splits: stage s{0,1}, split p{0,1,2}: (s*3+p)*10240   (128 rows * 80B, padded)
//   B splits: 61440 + (s*3+p)*20480                          (256 rows * 80B)
//   x stage : 184320 + s*18432                               (128 rows * 144B fp32)
#define A_OFF(s, p) ((((s) * 3) + (p)) * 10240)
#define B_OFF(s, p) (61440 + (((s) * 3) + (p)) * 20480)
#define X_OFF(s)    (184320 + (s) * 18432)
#define SMEM_BYTES  (221184 + 128)
#define HPITCH 264   // floats, epilogue h-stage pitch

// ---------------- device scratch ----------------
__device__ float  g_h[(size_t)MDIM * NDIM];        // 256 MB hidden
__device__ double g_sum[NDIM];
__device__ double g_sumsq[NDIM];
__device__ float  g_a[NDIM];
__device__ float  g_c[NDIM];
__device__ __nv_bfloat16 g_Bh[KDIM * NDIM];        // W1^T splits, [n][k]
__device__ __nv_bfloat16 g_Bm[KDIM * NDIM];
__device__ __nv_bfloat16 g_Bl[KDIM * NDIM];

// ---------------- PTX helpers (all sm_80-era, safe on sm_103 target) ---------
__device__ __forceinline__ uint32_t smem_u32(const void* p) {
    uint32_t a;
    asm("{ .reg .u64 t; cvta.to.shared.u64 t, %1; cvt.u32.u64 %0, t; }" : "=r"(a) : "l"(p));
    return a;
}
#define STS128(r0, r1, r2, r3, addr) \
    asm volatile("st.shared.v4.b32 [%0], {%1, %2, %3, %4};" \
                 :: "r"(addr), "r"(r0), "r"(r1), "r"(r2), "r"(r3) : "memory")
#define LDS128(r0, r1, r2, r3, addr) \
    asm volatile("ld.shared.v4.b32 {%0, %1, %2, %3}, [%4];" \
                 : "=r"(r0), "=r"(r1), "=r"(r2), "=r"(r3) : "r"(addr))
#define LDS32(r0, addr) \
    asm volatile("ld.shared.b32 %0, [%1];" : "=r"(r0) : "r"(addr))
#define STS64F(addr, x, y) \
    asm volatile("st.shared.v2.f32 [%0], {%1, %2};" :: "r"(addr), "f"(x), "f"(y) : "memory")

__device__ __forceinline__ void ldsm_x4(uint32_t* r, uint32_t addr) {
    asm volatile("ldmatrix.sync.aligned.m8n8.x4.shared.b16 {%0,%1,%2,%3}, [%4];"
                 : "=r"(r[0]), "=r"(r[1]), "=r"(r[2]), "=r"(r[3]) : "r"(addr));
}
__device__ __forceinline__ void mma16816(float* d, const uint32_t* a, const uint32_t* b) {
    asm volatile(
        "mma.sync.aligned.m16n8k16.row.col.f32.bf16.bf16.f32 "
        "{%0,%1,%2,%3}, {%4,%5,%6,%7}, {%8,%9}, {%0,%1,%2,%3};"
        : "+f"(d[0]), "+f"(d[1]), "+f"(d[2]), "+f"(d[3])
        : "r"(a[0]), "r"(a[1]), "r"(a[2]), "r"(a[3]), "r"(b[0]), "r"(b[1]));
}
__device__ __forceinline__ void cpasync16(uint32_t dst, const void* src) {
    asm volatile("cp.async.cg.shared.global [%0], [%1], 16;" :: "r"(dst), "l"(src));
}
#define CP_COMMIT() asm volatile("cp.async.commit_group;" ::: "memory")
#define CP_WAIT0()  asm volatile("cp.async.wait_group 0;" ::: "memory")

// bf16x3 split
__device__ __forceinline__ void split3(float v, uint32_t& h, uint32_t& m, uint32_t& l) {
    __nv_bfloat16 bh = __float2bfloat16_rn(v);
    float r = v - __bfloat162float(bh);
    __nv_bfloat16 bm = __float2bfloat16_rn(r);
    float r2 = r - __bfloat162float(bm);
    __nv_bfloat16 bl = __float2bfloat16_rn(r2);
    h = (uint32_t)__bfloat16_as_ushort(bh);
    m = (uint32_t)__bfloat16_as_ushort(bm);
    l = (uint32_t)__bfloat16_as_ushort(bl);
}
__device__ __forceinline__ const __nv_bfloat16* bsplit_ptr(int p) {
    return (p == 0) ? g_Bh : ((p == 1) ? g_Bm : g_Bl);
}

// ---------------------------------------------------------------------------
// K0: zero stats
// ---------------------------------------------------------------------------
__global__ void zero_stats_kernel() {
    int j = threadIdx.x;
    g_sum[j] = 0.0;
    g_sumsq[j] = 0.0;
}

// ---------------------------------------------------------------------------
// K1: split W1 [k][n] fp32 -> 3 bf16 matrices [n][k]
// ---------------------------------------------------------------------------
__global__ void splitB_kernel(const float* __restrict__ W1) {
    int e = blockIdx.x * blockDim.x + threadIdx.x;   // 0..131071
#pragma unroll
    for (int t = 0; t < 2; t++) {
        int i = e + t * 131072;                      // i = k*512 + n
        int k = i >> 9, n = i & 511;
        uint32_t h, m, l;
        split3(W1[i], h, m, l);
        int o = n * KDIM + k;
        g_Bh[o] = __ushort_as_bfloat16((unsigned short)h);
        g_Bm[o] = __ushort_as_bfloat16((unsigned short)m);
        g_Bl[o] = __ushort_as_bfloat16((unsigned short)l);
    }
}

// ---------------------------------------------------------------------------
// K2: bf16x3 HMMA GEMM  h = x @ W1 + b1, fused column stats
// ---------------------------------------------------------------------------
__device__ __forceinline__ void issue_loads(const float* __restrict__ X, uint32_t base,
                                            int m0, int n0, int c, int xr, int xsb,
                                            int bn, int bs) {
    const int s = c & 1;
    const float* xrow = X + (size_t)(m0 + xr) * KDIM + c * KC + xsb * 4;
    uint32_t xdst = base + X_OFF(s) + xr * 144 + xsb * 16;
#pragma unroll
    for (int q = 0; q < 4; q++) cpasync16(xdst + q * 16, xrow + q * 4);
#pragma unroll
    for (int p = 0; p < 3; p++) {
        const __nv_bfloat16* gb = bsplit_ptr(p);
#pragma unroll
        for (int q = 0; q < 4; q++) {
            int n = q * 64 + bn;
            const __nv_bfloat16* src = gb + (size_t)(n0 + n) * KDIM + c * KC + bs * 8;
            cpasync16(base + B_OFF(s, p) + n * 80 + bs * 16, src);
        }
    }
    CP_COMMIT();
}

__device__ __forceinline__ void convert_x(uint32_t base, int c, int xr, int xsb) {
    const int s = c & 1;
    uint32_t xsrc = base + X_OFF(s) + xr * 144 + xsb * 16;
    uint32_t ph[8], pm[8], pl[8];
#pragma unroll
    for (int q = 0; q < 4; q++) {
        uint32_t u0, u1, u2, u3;
        LDS128(u0, u1, u2, u3, xsrc + q * 16);
        float f0 = __uint_as_float(u0), f1 = __uint_as_float(u1);
        float f2 = __uint_as_float(u2), f3 = __uint_as_float(u3);
        uint32_t h0, m0b, l0, h1, m1b, l1;
        split3(f0, h0, m0b, l0);
        split3(f1, h1, m1b, l1);
        ph[q * 2] = h0 | (h1 << 16);
        pm[q * 2] = m0b | (m1b << 16);
        pl[q * 2] = l0 | (l1 << 16);
        split3(f2, h0, m0b, l0);
        split3(f3, h1, m1b, l1);
        ph[q * 2 + 1] = h0 | (h1 << 16);
        pm[q * 2 + 1] = m0b | (m1b << 16);
        pl[q * 2 + 1] = l0 | (l1 << 16);
    }
    uint32_t rowoff = (uint32_t)(xr * 80 + xsb * 8);
    STS128(ph[0], ph[1], ph[2], ph[3], base + A_OFF(s, 0) + rowoff);
    STS128(ph[4], ph[5], ph[6], ph[7], base + A_OFF(s, 0) + rowoff + 16);
    STS128(pm[0], pm[1], pm[2], pm[3], base + A_OFF(s, 1) + rowoff);
    STS128(pm[4], pm[5], pm[6], pm[7], base + A_OFF(s, 1) + rowoff + 16);
    STS128(pl[0], pl[1], pl[2], pl[3], base + A_OFF(s, 2) + rowoff);
    STS128(pl[4], pl[5], pl[6], pl[7], base + A_OFF(s, 2) + rowoff + 16);
}

__global__ void __launch_bounds__(256, 1)
gemm_kernel(const float* __restrict__ X, const float* __restrict__ b1) {
    extern __shared__ char dyn[];
    __shared__ float sbias[TILE_N];

    const uint32_t base = (smem_u32(dyn) + 127u) & ~127u;
    const int tid = threadIdx.x;
    const int wid = tid >> 5;
    const int lane = tid & 31;
    const int m0 = blockIdx.y * TILE_M;
    const int n0 = blockIdx.x * TILE_N;

    sbias[tid] = b1[n0 + tid];

    const int xr = tid >> 1;
    const int xsb = (tid & 1) * 4;
    const int bn = tid >> 2;
    const int bs = tid & 3;

    const int wm = (wid >> 2) * 64;
    const int wn = (wid & 3) * 64;

    float acc[4][8][4];
#pragma unroll
    for (int i = 0; i < 4; i++)
#pragma unroll
        for (int j = 0; j < 8; j++)
#pragma unroll
            for (int q = 0; q < 4; q++) acc[i][j][q] = 0.f;

    // prologue
    issue_loads(X, base, m0, n0, 0, xr, xsb, bn, bs);
    CP_WAIT0();
    convert_x(base, 0, xr, xsb);
    __syncthreads();

    // lane-constant address components
    const int arow = lane & 15;
    const int acolh = (lane >> 4) * 16;      // bytes: +8 bf16 for lanes 16-31
    const int brow = lane >> 2;
    const int bcol = (lane & 3) * 4;         // bytes: (lane%4)*2 bf16

    for (int c = 0; c < NCHUNK; c++) {
        const int s = c & 1;
        if (c + 1 < NCHUNK) issue_loads(X, base, m0, n0, c + 1, xr, xsb, bn, bs);

#pragma unroll
        for (int k16 = 0; k16 < 2; k16++) {
            const uint32_t koffA = (uint32_t)(k16 * 32 + acolh);
            const uint32_t koffB = (uint32_t)(k16 * 32 + bcol);
            uint32_t aF[2][4][4], bF[2][8][2];
            // slot0 = H, slot1 = M
#pragma unroll
            for (int slot = 0; slot < 2; slot++) {
#pragma unroll
                for (int i = 0; i < 4; i++)
                    ldsm_x4(aF[slot][i],
                            base + A_OFF(s, slot) + (uint32_t)((wm + i * 16 + arow) * 80) + koffA);
#pragma unroll
                for (int j = 0; j < 8; j++) {
                    uint32_t ba = base + B_OFF(s, slot) +
                                  (uint32_t)((wn + j * 8 + brow) * 80) + koffB;
                    LDS32(bF[slot][j][0], ba);
                    LDS32(bF[slot][j][1], ba + 16);
                }
            }
            // G1: (H,H) (H,M) (M,H) (M,M)
#pragma unroll
            for (int pa = 0; pa < 2; pa++)
#pragma unroll
                for (int pb = 0; pb < 2; pb++)
#pragma unroll
                    for (int i = 0; i < 4; i++)
#pragma unroll
                        for (int j = 0; j < 8; j++)
                            mma16816(acc[i][j], aF[pa][i], bF[pb][j]);
            // G2: slot1 <- L; products (H,L) and (L,H)
#pragma unroll
            for (int i = 0; i < 4; i++)
                ldsm_x4(aF[1][i],
                        base + A_OFF(s, 2) + (uint32_t)((wm + i * 16 + arow) * 80) + koffA);
#pragma unroll
            for (int j = 0; j < 8; j++) {
                uint32_t ba = base + B_OFF(s, 2) + (uint32_t)((wn + j * 8 + brow) * 80) + koffB;
                LDS32(bF[1][j][0], ba);
                LDS32(bF[1][j][1], ba + 16);
            }
#pragma unroll
            for (int i = 0; i < 4; i++)
#pragma unroll
                for (int j = 0; j < 8; j++) {
                    mma16816(acc[i][j], aF[0][i], bF[1][j]);
                    mma16816(acc[i][j], aF[1][i], bF[0][j]);
                }
        }

        if (c + 1 < NCHUNK) {
            CP_WAIT0();
            convert_x(base, c + 1, xr, xsb);
        }
        __syncthreads();
    }

    // ---------------- epilogue: stage accum -> smem ----------------
#pragma unroll
    for (int i = 0; i < 4; i++)
#pragma unroll
        for (int j = 0; j < 8; j++) {
            int r0 = wm + i * 16 + (lane >> 2);
            int c0 = wn + j * 8 + (lane & 3) * 2;
            uint32_t a0 = base + (uint32_t)((r0 * HPITCH + c0) * 4);
            STS64F(a0, acc[i][j][0], acc[i][j][1]);
            STS64F(a0 + 8 * HPITCH * 4, acc[i][j][2], acc[i][j][3]);
        }
    __syncthreads();

    // coalesced global write with bias
#pragma unroll 4
    for (int t = 0; t < 32; t++) {
        int idx = tid + t * 256;
        int r = idx >> 6, cs = idx & 63;
        uint32_t u0, u1, u2, u3;
        LDS128(u0, u1, u2, u3, base + (uint32_t)((r * HPITCH + cs * 4) * 4));
        float4 bv = *(const float4*)&sbias[cs * 4];
        float4 o;
        o.x = __uint_as_float(u0) + bv.x;
        o.y = __uint_as_float(u1) + bv.y;
        o.z = __uint_as_float(u2) + bv.z;
        o.w = __uint_as_float(u3) + bv.w;
        *(float4*)&g_h[(size_t)(m0 + r) * NDIM + n0 + cs * 4] = o;
    }

    // fused column stats (thread tid -> column n0+tid)
    float bcolv = sbias[tid];
    float ss = 0.f, s2 = 0.f;
#pragma unroll 8
    for (int r = 0; r < 128; r++) {
        uint32_t u;
        LDS32(u, base + (uint32_t)((r * HPITCH + tid) * 4));
        float v = __uint_as_float(u) + bcolv;
        ss += v;
        s2 = fmaf(v, v, s2);
    }
    atomicAdd(&g_sum[n0 + tid], (double)ss);
    atomicAdd(&g_sumsq[n0 + tid], (double)s2);
}

// ---------------------------------------------------------------------------
// K3: finalize BN affine
// ---------------------------------------------------------------------------
__global__ void finalize_kernel(const float* __restrict__ gamma,
                                const float* __restrict__ beta) {
    int j = threadIdx.x;
    double mu = g_sum[j] / (double)MDIM;
    double var = g_sumsq[j] / (double)MDIM - mu * mu;
    double a = (double)gamma[j] / sqrt(var + 1e-5);
    g_a[j] = (float)a;
    g_c[j] = (float)((double)beta[j] - mu * a);
}

// ---------------------------------------------------------------------------
// K4: heads (one warp per row)
// ---------------------------------------------------------------------------
__global__ void __launch_bounds__(256) heads_kernel(const float* __restrict__ Hbuf,
                                                    const float* __restrict__ Wa,
                                                    const float* __restrict__ ba,
                                                    const float* __restrict__ Wb,
                                                    const float* __restrict__ bb,
                                                    float* __restrict__ out) {
    const int row = (int)((blockIdx.x * blockDim.x + threadIdx.x) >> 5);
    const int lane = threadIdx.x & 31;
    if (row >= MDIM) return;
    const int n = row & (NNODES - 1);
    const bool isA = (n < HALFN);

    const float4* h4 = (const float4*)(Hbuf + (size_t)row * NDIM);
    const float4* ga4 = (const float4*)g_a;
    const float4* gc4 = (const float4*)g_c;

    float acc[5] = {0.f, 0.f, 0.f, 0.f, 0.f};
#pragma unroll
    for (int i = 0; i < 4; i++) {
        int j4 = i * 32 + lane;
        float4 v = h4[j4];
        float4 a4 = ga4[j4];
        float4 c4 = gc4[j4];
        float t[4];
        t[0] = fmaxf(fmaf(v.x, a4.x, c4.x), 0.f);
        t[1] = fmaxf(fmaf(v.y, a4.y, c4.y), 0.f);
        t[2] = fmaxf(fmaf(v.z, a4.z, c4.z), 0.f);
        t[3] = fmaxf(fmaf(v.w, a4.w, c4.w), 0.f);
        if (isA) {
#pragma unroll
            for (int e = 0; e < 4; e++) {
                int j = j4 * 4 + e;
#pragma unroll
                for (int c = 0; c < 3; c++) acc[c] = fmaf(t[e], Wa[j * 3 + c], acc[c]);
            }
        } else {
#pragma unroll
            for (int e = 0; e < 4; e++) {
                int j = j4 * 4 + e;
#pragma unroll
                for (int c = 0; c < 5; c++) acc[c] = fmaf(t[e], Wb[j * 5 + c], acc[c]);
            }
        }
    }
#pragma unroll
    for (int off = 16; off > 0; off >>= 1) {
#pragma unroll
        for (int c = 0; c < 5; c++) acc[c] += __shfl_down_sync(0xFFFFFFFFu, acc[c], off);
    }
    if (lane == 0) {
        int C = isA ? 3 : 5;
        const float* bvec = isA ? ba : bb;
        int best = 0;
        float bestv = acc[0] + bvec[0];
#pragma unroll
        for (int c = 1; c < 5; c++) {
            if (c < C) {
                float lv = acc[c] + bvec[c];
                if (lv > bestv) { bestv = lv; best = c; }
            }
        }
        out[row] = (float)best;
    }
}

// ---------------------------------------------------------------------------
// launch
// ---------------------------------------------------------------------------
extern "C" void kernel_launch(void* const* d_in, const int* in_sizes, int n_in,
                              void* d_out, int out_size) {
    const float* x     = (const float*)d_in[0];
    const float* W1    = (const float*)d_in[1];
    const float* b1    = (const float*)d_in[2];
    const float* gamma = (const float*)d_in[3];
    const float* beta  = (const float*)d_in[4];
    const float* Wa    = (const float*)d_in[5];
    const float* ba    = (const float*)d_in[6];
    const float* Wb    = (const float*)d_in[7];
    const float* bb    = (const float*)d_in[8];
    float* out = (float*)d_out;

    float* Hbuf;
    cudaGetSymbolAddress((void**)&Hbuf, g_h);

    cudaFuncSetAttribute(gemm_kernel, cudaFuncAttributeMaxDynamicSharedMemorySize,
                         SMEM_BYTES);

    zero_stats_kernel<<<1, NDIM>>>();
    splitB_kernel<<<512, 256>>>(W1);

    dim3 ggrid(NDIM / TILE_N, MDIM / TILE_M);   // (2, 1024)
    gemm_kernel<<<ggrid, 256, SMEM_BYTES>>>(x, b1);

    finalize_kernel<<<1, NDIM>>>(gamma, beta);

    heads_kernel<<<(MDIM * 32) / 256, 256>>>(Hbuf, Wa, ba, Wb, bb, out);
}

// round 4
// speedup vs baseline: 1.2753x; 1.1166x over previous
#include <cuda_runtime.h>
#include <cuda_fp16.h>
#include <stdint.h>
#include <math.h>

// ---------------- problem constants ----------------
#define MDIM 131072   // B*N rows
#define KDIM 512      // D
#define NDIM 512      // H
#define NNODES 2048
#define HALFN 1024

#define TILE_M 128
#define TILE_N 128
#define KC 32
#define NCHUNK 16
#define THREADS 256

// smem layout (bytes from 128-aligned dynamic base):
//   A splits (x): stage s{0,1}, split p{0,1}: (s*2+p)*10240   (128 rows * 80B)
//   B splits (W): 40960 + (s*2+p)*10240                        (128 rows * 80B)
//   x fp32 stage: 81920 + s*18432                              (128 rows * 144B)
#define A_OFF(s, p) ((((s) * 2) + (p)) * 10240)
#define B_OFF(s, p) (40960 + (((s) * 2) + (p)) * 10240)
#define X_OFF(s)    (81920 + (s) * 18432)
#define SMEM_BYTES  (118784 + 128)
#define HPITCH 132            // floats, epilogue staging pitch
#define SCALE_UP 4096.0f
#define SCALE_DN (1.0f / 4096.0f)

// ---------------- device scratch ----------------
__device__ float  g_h[(size_t)MDIM * NDIM];        // 256 MB hidden
__device__ float  g_ps[2048 * NDIM];               // per-slab column sums
__device__ float  g_pq[2048 * NDIM];               // per-slab column sumsq
__device__ float  g_a[NDIM];
__device__ float  g_c[NDIM];
__device__ __half g_Bh[KDIM * NDIM];               // W1^T splits, [n][k]
__device__ __half g_Bm[KDIM * NDIM];               // scaled by 4096

// ---------------- PTX helpers ----------------
__device__ __forceinline__ uint32_t smem_u32(const void* p) {
    uint32_t a;
    asm("{ .reg .u64 t; cvta.to.shared.u64 t, %1; cvt.u32.u64 %0, t; }" : "=r"(a) : "l"(p));
    return a;
}
#define STS128(r0, r1, r2, r3, addr) \
    asm volatile("st.shared.v4.b32 [%0], {%1, %2, %3, %4};" \
                 :: "r"(addr), "r"(r0), "r"(r1), "r"(r2), "r"(r3) : "memory")
#define LDS128(r0, r1, r2, r3, addr) \
    asm volatile("ld.shared.v4.b32 {%0, %1, %2, %3}, [%4];" \
                 : "=r"(r0), "=r"(r1), "=r"(r2), "=r"(r3) : "r"(addr))
#define LDS32(r0, addr) \
    asm volatile("ld.shared.b32 %0, [%1];" : "=r"(r0) : "r"(addr))
#define STS64F(addr, x, y) \
    asm volatile("st.shared.v2.f32 [%0], {%1, %2};" :: "r"(addr), "f"(x), "f"(y) : "memory")

__device__ __forceinline__ void ldsm_x4(uint32_t* r, uint32_t addr) {
    asm volatile("ldmatrix.sync.aligned.m8n8.x4.shared.b16 {%0,%1,%2,%3}, [%4];"
                 : "=r"(r[0]), "=r"(r[1]), "=r"(r[2]), "=r"(r[3]) : "r"(addr));
}
__device__ __forceinline__ void mma16816(float* d, const uint32_t* a, const uint32_t* b) {
    asm volatile(
        "mma.sync.aligned.m16n8k16.row.col.f32.f16.f16.f32 "
        "{%0,%1,%2,%3}, {%4,%5,%6,%7}, {%8,%9}, {%0,%1,%2,%3};"
        : "+f"(d[0]), "+f"(d[1]), "+f"(d[2]), "+f"(d[3])
        : "r"(a[0]), "r"(a[1]), "r"(a[2]), "r"(a[3]), "r"(b[0]), "r"(b[1]));
}
__device__ __forceinline__ void cpasync16(uint32_t dst, const void* src) {
    asm volatile("cp.async.cg.shared.global [%0], [%1], 16;" :: "r"(dst), "l"(src));
}
#define CP_COMMIT() asm volatile("cp.async.commit_group;" ::: "memory")
#define CP_WAIT0()  asm volatile("cp.async.wait_group 0;" ::: "memory")

// scaled fp16x2 split: v = h + m*2^-12 (m stored pre-scaled by 2^12)
__device__ __forceinline__ void split2(float v, uint32_t& h, uint32_t& m) {
    __half hh = __float2half_rn(v);
    float r = (v - __half2float(hh)) * SCALE_UP;
    __half hm = __float2half_rn(r);
    h = (uint32_t)__half_as_ushort(hh);
    m = (uint32_t)__half_as_ushort(hm);
}

// ---------------------------------------------------------------------------
// K1: split W1 [k][n] fp32 -> 2 fp16 matrices [n][k] (m-split scaled 4096)
// ---------------------------------------------------------------------------
__global__ void splitB_kernel(const float* __restrict__ W1) {
    int i = blockIdx.x * blockDim.x + threadIdx.x;   // 0..262143 = k*512+n
    int k = i >> 9, n = i & 511;
    uint32_t h, m;
    split2(W1[i], h, m);
    int o = n * KDIM + k;
    g_Bh[o] = __ushort_as_half((unsigned short)h);
    g_Bm[o] = __ushort_as_half((unsigned short)m);
}

// ---------------------------------------------------------------------------
// K2: fp16x2 HMMA GEMM  h = x @ W1 + b1, fused per-slab column stats
// ---------------------------------------------------------------------------
__device__ __forceinline__ void issue_loads(const float* __restrict__ X, uint32_t base,
                                            int m0, int n0, int c, int tid) {
    const int s = c & 1;
    // x: 128 rows x 128B (8 segs of 16B); 2 threads/row x 4 segs
    {
        int row = tid >> 1;
        int sb = (tid & 1) * 4;
        const float* src = X + (size_t)(m0 + row) * KDIM + c * KC;
        uint32_t dst = base + X_OFF(s) + row * 144;
#pragma unroll
        for (int q = 0; q < 4; q++)
            cpasync16(dst + (sb + q) * 16, src + (sb + q) * 4);
    }
    // B: 2 splits x 128 rows x 64B (4 segs)
    {
        int p = tid >> 7;
        int r = tid & 127;
        const __half* gb = (p == 0) ? g_Bh : g_Bm;
        const __half* src = gb + (size_t)(n0 + r) * KDIM + c * KC;
        uint32_t dst = base + B_OFF(s, p) + r * 80;
#pragma unroll
        for (int q = 0; q < 4; q++)
            cpasync16(dst + q * 16, src + q * 8);
    }
    CP_COMMIT();
}

__device__ __forceinline__ void convert_x(uint32_t base, int c, int tid) {
    const int s = c & 1;
    int row = tid >> 1;
    int fo = (tid & 1) * 16;                 // 16 floats per thread
    uint32_t xsrc = base + X_OFF(s) + row * 144 + fo * 4;
    uint32_t ph[8], pm[8];
#pragma unroll
    for (int q = 0; q < 4; q++) {
        uint32_t u0, u1, u2, u3;
        LDS128(u0, u1, u2, u3, xsrc + q * 16);
        uint32_t h0, m0v, h1, m1v;
        split2(__uint_as_float(u0), h0, m0v);
        split2(__uint_as_float(u1), h1, m1v);
        ph[q * 2] = h0 | (h1 << 16);
        pm[q * 2] = m0v | (m1v << 16);
        split2(__uint_as_float(u2), h0, m0v);
        split2(__uint_as_float(u3), h1, m1v);
        ph[q * 2 + 1] = h0 | (h1 << 16);
        pm[q * 2 + 1] = m0v | (m1v << 16);
    }
    uint32_t ro = (uint32_t)(row * 80 + fo * 2);
    STS128(ph[0], ph[1], ph[2], ph[3], base + A_OFF(s, 0) + ro);
    STS128(ph[4], ph[5], ph[6], ph[7], base + A_OFF(s, 0) + ro + 16);
    STS128(pm[0], pm[1], pm[2], pm[3], base + A_OFF(s, 1) + ro);
    STS128(pm[4], pm[5], pm[6], pm[7], base + A_OFF(s, 1) + ro + 16);
}

__global__ void __launch_bounds__(THREADS, 1)
gemm_kernel(const float* __restrict__ X, const float* __restrict__ b1) {
    extern __shared__ char dyn[];
    __shared__ float sbias[TILE_N];

    const uint32_t base = (smem_u32(dyn) + 127u) & ~127u;
    const int tid = threadIdx.x;
    const int wid = tid >> 5;
    const int lane = tid & 31;
    const int m0 = blockIdx.y * TILE_M;
    const int n0 = blockIdx.x * TILE_N;

    if (tid < TILE_N) sbias[tid] = b1[n0 + tid];

    const int wm = (wid & 3) * 32;     // 4 m-positions of 32
    const int wn = (wid >> 2) * 64;    // 2 n-positions of 64

    float a1[2][8][4], a2[2][8][4];
#pragma unroll
    for (int i = 0; i < 2; i++)
#pragma unroll
        for (int j = 0; j < 8; j++)
#pragma unroll
            for (int q = 0; q < 4; q++) { a1[i][j][q] = 0.f; a2[i][j][q] = 0.f; }

    // prologue
    issue_loads(X, base, m0, n0, 0, tid);
    CP_WAIT0();
    convert_x(base, 0, tid);
    __syncthreads();

    const int arow = lane & 15;
    const int acolh = (lane >> 4) * 16;    // bytes
    const int brow = lane >> 2;
    const int bcol = (lane & 3) * 4;       // bytes

    for (int c = 0; c < NCHUNK; c++) {
        const int s = c & 1;
        if (c + 1 < NCHUNK) issue_loads(X, base, m0, n0, c + 1, tid);

#pragma unroll
        for (int k16 = 0; k16 < 2; k16++) {
            const uint32_t koA = (uint32_t)(k16 * 32 + acolh);
            const uint32_t koB = (uint32_t)(k16 * 32 + bcol);
            uint32_t aH[2][4], aM[2][4], bH[8][2], bM[8][2];
#pragma unroll
            for (int i = 0; i < 2; i++) {
                uint32_t ra = (uint32_t)((wm + i * 16 + arow) * 80);
                ldsm_x4(aH[i], base + A_OFF(s, 0) + ra + koA);
                ldsm_x4(aM[i], base + A_OFF(s, 1) + ra + koA);
            }
#pragma unroll
            for (int j = 0; j < 8; j++) {
                uint32_t rb = (uint32_t)((wn + j * 8 + brow) * 80);
                LDS32(bH[j][0], base + B_OFF(s, 0) + rb + koB);
                LDS32(bH[j][1], base + B_OFF(s, 0) + rb + koB + 16);
                LDS32(bM[j][0], base + B_OFF(s, 1) + rb + koB);
                LDS32(bM[j][1], base + B_OFF(s, 1) + rb + koB + 16);
            }
            // product 1: H*H -> acc1
#pragma unroll
            for (int i = 0; i < 2; i++)
#pragma unroll
                for (int j = 0; j < 8; j++) mma16816(a1[i][j], aH[i], bH[j]);
            // products 2,3: H*M + M*H -> acc2 (scaled 2^12)
#pragma unroll
            for (int i = 0; i < 2; i++)
#pragma unroll
                for (int j = 0; j < 8; j++) mma16816(a2[i][j], aH[i], bM[j]);
#pragma unroll
            for (int i = 0; i < 2; i++)
#pragma unroll
                for (int j = 0; j < 8; j++) mma16816(a2[i][j], aM[i], bH[j]);
        }

        if (c + 1 < NCHUNK) {
            CP_WAIT0();
            convert_x(base, c + 1, tid);
        }
        __syncthreads();
    }

    // ---------------- epilogue: combine + stage to smem ----------------
#pragma unroll
    for (int i = 0; i < 2; i++)
#pragma unroll
        for (int j = 0; j < 8; j++) {
            int r0 = wm + i * 16 + (lane >> 2);
            int c0 = wn + j * 8 + (lane & 3) * 2;
            float v0 = a1[i][j][0] + a2[i][j][0] * SCALE_DN;
            float v1 = a1[i][j][1] + a2[i][j][1] * SCALE_DN;
            float v2 = a1[i][j][2] + a2[i][j][2] * SCALE_DN;
            float v3 = a1[i][j][3] + a2[i][j][3] * SCALE_DN;
            STS64F(base + (uint32_t)((r0 * HPITCH + c0) * 4), v0, v1);
            STS64F(base + (uint32_t)(((r0 + 8) * HPITCH + c0) * 4), v2, v3);
        }
    __syncthreads();

    // coalesced global write with bias
#pragma unroll 4
    for (int t = 0; t < 16; t++) {
        int fidx = tid + t * 256;          // float4 index
        int r = fidx >> 5, cs = fidx & 31;
        uint32_t u0, u1, u2, u3;
        LDS128(u0, u1, u2, u3, base + (uint32_t)((r * HPITCH + cs * 4) * 4));
        float4 bv = *(const float4*)&sbias[cs * 4];
        float4 o;
        o.x = __uint_as_float(u0) + bv.x;
        o.y = __uint_as_float(u1) + bv.y;
        o.z = __uint_as_float(u2) + bv.z;
        o.w = __uint_as_float(u3) + bv.w;
        *(float4*)&g_h[(size_t)(m0 + r) * NDIM + n0 + cs * 4] = o;
    }

    // per-slab column stats (idempotent partials; 2 threads per column)
    {
        int col = tid & 127;
        int half = tid >> 7;
        float bcolv = sbias[col];
        float ss = 0.f, s2 = 0.f;
#pragma unroll 8
        for (int r = half * 64; r < half * 64 + 64; r++) {
            uint32_t u;
            LDS32(u, base + (uint32_t)((r * HPITCH + col) * 4));
            float v = __uint_as_float(u) + bcolv;
            ss += v;
            s2 = fmaf(v, v, s2);
        }
        int slot = (blockIdx.y * 2 + half) * NDIM + n0 + col;
        g_ps[slot] = ss;
        g_pq[slot] = s2;
    }
}

// ---------------------------------------------------------------------------
// K3: finalize BN affine (one warp per column, fp64 reduce of 2048 partials)
// ---------------------------------------------------------------------------
__global__ void __launch_bounds__(256) finalize_kernel(const float* __restrict__ gamma,
                                                       const float* __restrict__ beta) {
    int col = blockIdx.x * 8 + (threadIdx.x >> 5);
    int lane = threadIdx.x & 31;
    double s = 0.0, q = 0.0;
    for (int i = lane; i < 2048; i += 32) {
        s += (double)g_ps[i * NDIM + col];
        q += (double)g_pq[i * NDIM + col];
    }
#pragma unroll
    for (int off = 16; off > 0; off >>= 1) {
        s += __shfl_down_sync(0xFFFFFFFFu, s, off);
        q += __shfl_down_sync(0xFFFFFFFFu, q, off);
    }
    if (lane == 0) {
        double mu = s / (double)MDIM;
        double var = q / (double)MDIM - mu * mu;
        double a = (double)gamma[col] / sqrt(var + 1e-5);
        g_a[col] = (float)a;
        g_c[col] = (float)((double)beta[col] - mu * a);
    }
}

// ---------------------------------------------------------------------------
// K4: heads (one warp per row)
// ---------------------------------------------------------------------------
__global__ void __launch_bounds__(256) heads_kernel(const float* __restrict__ Hbuf,
                                                    const float* __restrict__ Wa,
                                                    const float* __restrict__ ba,
                                                    const float* __restrict__ Wb,
                                                    const float* __restrict__ bb,
                                                    float* __restrict__ out) {
    const int row = (int)((blockIdx.x * blockDim.x + threadIdx.x) >> 5);
    const int lane = threadIdx.x & 31;
    if (row >= MDIM) return;
    const int n = row & (NNODES - 1);
    const bool isA = (n < HALFN);

    const float4* h4 = (const float4*)(Hbuf + (size_t)row * NDIM);
    const float4* ga4 = (const float4*)g_a;
    const float4* gc4 = (const float4*)g_c;

    float acc[5] = {0.f, 0.f, 0.f, 0.f, 0.f};
#pragma unroll
    for (int i = 0; i < 4; i++) {
        int j4 = i * 32 + lane;
        float4 v = h4[j4];
        float4 a4 = ga4[j4];
        float4 c4 = gc4[j4];
        float t[4];
        t[0] = fmaxf(fmaf(v.x, a4.x, c4.x), 0.f);
        t[1] = fmaxf(fmaf(v.y, a4.y, c4.y), 0.f);
        t[2] = fmaxf(fmaf(v.z, a4.z, c4.z), 0.f);
        t[3] = fmaxf(fmaf(v.w, a4.w, c4.w), 0.f);
        if (isA) {
#pragma unroll
            for (int e = 0; e < 4; e++) {
                int j = j4 * 4 + e;
#pragma unroll
                for (int c = 0; c < 3; c++) acc[c] = fmaf(t[e], Wa[j * 3 + c], acc[c]);
            }
        } else {
#pragma unroll
            for (int e = 0; e < 4; e++) {
                int j = j4 * 4 + e;
#pragma unroll
                for (int c = 0; c < 5; c++) acc[c] = fmaf(t[e], Wb[j * 5 + c], acc[c]);
            }
        }
    }
#pragma unroll
    for (int off = 16; off > 0; off >>= 1) {
#pragma unroll
        for (int c = 0; c < 5; c++) acc[c] += __shfl_down_sync(0xFFFFFFFFu, acc[c], off);
    }
    if (lane == 0) {
        int C = isA ? 3 : 5;
        const float* bvec = isA ? ba : bb;
        int best = 0;
        float bestv = acc[0] + bvec[0];
#pragma unroll
        for (int c = 1; c < 5; c++) {
            if (c < C) {
                float lv = acc[c] + bvec[c];
                if (lv > bestv) { bestv = lv; best = c; }
            }
        }
        out[row] = (float)best;
    }
}

// ---------------------------------------------------------------------------
// launch  (4 kernels; all idempotent -> graph-safe, no zeroing pass)
// ---------------------------------------------------------------------------
extern "C" void kernel_launch(void* const* d_in, const int* in_sizes, int n_in,
                              void* d_out, int out_size) {
    const float* x     = (const float*)d_in[0];
    const float* W1    = (const float*)d_in[1];
    const float* b1    = (const float*)d_in[2];
    const float* gamma = (const float*)d_in[3];
    const float* beta  = (const float*)d_in[4];
    const float* Wa    = (const float*)d_in[5];
    const float* ba    = (const float*)d_in[6];
    const float* Wb    = (const float*)d_in[7];
    const float* bb    = (const float*)d_in[8];
    float* out = (float*)d_out;

    float* Hbuf;
    cudaGetSymbolAddress((void**)&Hbuf, g_h);

    cudaFuncSetAttribute(gemm_kernel, cudaFuncAttributeMaxDynamicSharedMemorySize,
                         SMEM_BYTES);

    splitB_kernel<<<1024, 256>>>(W1);

    dim3 ggrid(NDIM / TILE_N, MDIM / TILE_M);   // (4, 1024)
    gemm_kernel<<<ggrid, THREADS, SMEM_BYTES>>>(x, b1);

    finalize_kernel<<<NDIM / 8, 256>>>(gamma, beta);

    heads_kernel<<<(MDIM * 32) / 256, 256>>>(Hbuf, Wa, ba, Wb, bb, out);
}